// round 1
// baseline (speedup 1.0000x reference)
#include <cuda_runtime.h>
#include <math.h>

#define NNODES 100000
#define CIN    256
#define NHEADS 4
#define DHEAD  64
#define TILE   64
#define NT     ((NNODES + TILE - 1) / TILE)   // 1563
#define BPH    37                              // blocks per head -> 148 blocks total
#define XSS    260                             // xs smem row stride (floats), 16B aligned, bank-spread
#define KST    68                              // ks/qs smem row stride (floats), 16B aligned, bank-spread

// ---------------- deterministic scratch (no atomics) ----------------
__device__ float g_part_kvs[BPH][NHEADS * DHEAD * CIN];   // per-block kv partials
__device__ float g_part_kss[BPH][NHEADS * DHEAD];         // per-block ks_sum partials
__device__ float g_part_cs [BPH][CIN];                    // per-block colsum partials (head-0 blocks)
__device__ float g_kvs   [NHEADS * DHEAD * CIN];
__device__ float g_kssum [NHEADS * DHEAD];
__device__ float g_colsum[CIN];

extern __shared__ float smf[];

// =====================================================================
// Phase A: k-projection + normalize + kv/ks_sum/colsum accumulation
// grid = (BPH, NHEADS), 256 threads, ~218KB dynamic smem
// =====================================================================
__global__ __launch_bounds__(256, 1)
void phaseA_kernel(const float* __restrict__ x,
                   const float* __restrict__ Wk,
                   const float* __restrict__ bk)
{
    const int h   = blockIdx.y;
    const int bx  = blockIdx.x;
    const int tid = threadIdx.x;
    const int tx  = tid & 15;
    const int ty  = tid >> 4;

    float* xs   = smf;                      // [TILE][XSS]
    float* wt   = xs  + TILE * XSS;         // [CIN][DHEAD]  Wk^T chunk for this head
    float* kv   = wt  + CIN * DHEAD;        // [DHEAD][CIN]  kv accumulator
    float* ks   = kv  + DHEAD * CIN;        // [TILE][KST]   normalized k tile
    float* bias = ks  + TILE * KST;         // [DHEAD]
    float* kss  = bias + DHEAD;             // [DHEAD] ks_sum accumulator
    float* cs   = kss + DHEAD;              // [CIN]   colsum accumulator
    float* red  = cs  + CIN;                // [256]
    float* inv  = red + 256;                // [TILE]

    // stage Wk^T for this head: wt[c][m] = Wk[(h*64+m)*256 + c]  (one-time)
    for (int i = tid; i < DHEAD * CIN; i += 256) {
        int c = i & (CIN - 1);
        int m = i >> 8;
        wt[c * DHEAD + m] = Wk[(h * DHEAD + m) * CIN + c];
    }
    for (int i = tid; i < DHEAD * CIN; i += 256) kv[i] = 0.f;
    if (tid < DHEAD) { bias[tid] = bk[h * DHEAD + tid]; kss[tid] = 0.f; }
    if (tid < CIN)   cs[tid] = 0.f;
    __syncthreads();

    for (int tile = bx; tile < NT; tile += BPH) {
        const int base  = tile * TILE;
        int valid = NNODES - base; if (valid > TILE) valid = TILE;

        // load x tile (row-major, float4, zero-pad tail rows)
        for (int i = tid; i < TILE * 64; i += 256) {
            int n  = i >> 6;
            int c4 = (i & 63) << 2;
            float4 v = make_float4(0.f, 0.f, 0.f, 0.f);
            if (n < valid)
                v = *reinterpret_cast<const float4*>(x + (size_t)(base + n) * CIN + c4);
            *reinterpret_cast<float4*>(xs + n * XSS + c4) = v;
        }
        __syncthreads();

        // ---- projection P[n][m] = sum_c xs[n][c] * wt[c][m]  (n=4ty+j, m=4tx+i)
        float acc[4][4];
        #pragma unroll
        for (int j = 0; j < 4; j++) { acc[j][0]=0.f; acc[j][1]=0.f; acc[j][2]=0.f; acc[j][3]=0.f; }
        {
            const float* xr0 = xs + (4 * ty + 0) * XSS;
            const float* xr1 = xr0 + XSS;
            const float* xr2 = xr1 + XSS;
            const float* xr3 = xr2 + XSS;
            const float* wp  = wt + 4 * tx;
            #pragma unroll 8
            for (int c = 0; c < CIN; c++) {
                float4 b = *reinterpret_cast<const float4*>(wp + c * DHEAD);
                float a0 = xr0[c], a1 = xr1[c], a2 = xr2[c], a3 = xr3[c];
                acc[0][0] += a0 * b.x; acc[0][1] += a0 * b.y; acc[0][2] += a0 * b.z; acc[0][3] += a0 * b.w;
                acc[1][0] += a1 * b.x; acc[1][1] += a1 * b.y; acc[1][2] += a1 * b.z; acc[1][3] += a1 * b.w;
                acc[2][0] += a2 * b.x; acc[2][1] += a2 * b.y; acc[2][2] += a2 * b.z; acc[2][3] += a2 * b.w;
                acc[3][0] += a3 * b.x; acc[3][1] += a3 * b.y; acc[3][2] += a3 * b.z; acc[3][3] += a3 * b.w;
            }
        }
        {
            float4 bb = *reinterpret_cast<const float4*>(bias + 4 * tx);
            #pragma unroll
            for (int j = 0; j < 4; j++) {
                float4 v;
                v.x = acc[j][0] + bb.x; v.y = acc[j][1] + bb.y;
                v.z = acc[j][2] + bb.z; v.w = acc[j][3] + bb.w;
                *reinterpret_cast<float4*>(ks + (4 * ty + j) * KST + 4 * tx) = v;
            }
        }
        __syncthreads();

        // ---- row norms (4 threads per row)
        {
            int n = tid >> 2, q = tid & 3;
            const float* kr = ks + n * KST + q * 16;
            float s = 0.f;
            #pragma unroll
            for (int i = 0; i < 16; i++) { float v = kr[i]; s += v * v; }
            red[n * 4 + q] = s;
        }
        __syncthreads();
        if (tid < TILE) {
            float s = red[tid*4] + red[tid*4+1] + red[tid*4+2] + red[tid*4+3];
            inv[tid] = (tid < valid) ? rsqrtf(s) : 0.f;
        }
        __syncthreads();
        // normalize k tile
        for (int i = tid; i < TILE * DHEAD; i += 256) {
            int n = i >> 6, m = i & 63;
            ks[n * KST + m] *= inv[n];
        }
        __syncthreads();

        // ---- ks_sum column partials
        {
            int m = tid & 63, rg = tid >> 6;
            float s = 0.f;
            #pragma unroll
            for (int r = 0; r < 16; r++) s += ks[(rg * 16 + r) * KST + m];
            red[rg * 64 + m] = s;
        }
        // ---- colsum of x (head-0 blocks only; covers every tile exactly once)
        if (h == 0) {
            float s = 0.f;
            #pragma unroll 8
            for (int n = 0; n < TILE; n++) s += xs[n * XSS + tid];
            cs[tid] += s;
        }
        __syncthreads();
        if (tid < DHEAD)
            kss[tid] += red[tid] + red[64 + tid] + red[128 + tid] + red[192 + tid];

        // ---- kv rank-update: kv[m][c] += sum_n ks[n][m] * xs[n][c]  (m=4ty+j, c=cc*64+4tx)
        {
            const float* kp = ks + 4 * ty;
            #pragma unroll
            for (int cc = 0; cc < 4; cc++) {
                float a2[4][4];
                #pragma unroll
                for (int j = 0; j < 4; j++) { a2[j][0]=0.f; a2[j][1]=0.f; a2[j][2]=0.f; a2[j][3]=0.f; }
                const float* xp = xs + cc * 64 + 4 * tx;
                #pragma unroll 8
                for (int n = 0; n < TILE; n++) {
                    float4 b = *reinterpret_cast<const float4*>(xp + n * XSS);
                    float s0 = kp[n*KST+0], s1 = kp[n*KST+1], s2 = kp[n*KST+2], s3 = kp[n*KST+3];
                    a2[0][0] += s0 * b.x; a2[0][1] += s0 * b.y; a2[0][2] += s0 * b.z; a2[0][3] += s0 * b.w;
                    a2[1][0] += s1 * b.x; a2[1][1] += s1 * b.y; a2[1][2] += s1 * b.z; a2[1][3] += s1 * b.w;
                    a2[2][0] += s2 * b.x; a2[2][1] += s2 * b.y; a2[2][2] += s2 * b.z; a2[2][3] += s2 * b.w;
                    a2[3][0] += s3 * b.x; a2[3][1] += s3 * b.y; a2[3][2] += s3 * b.z; a2[3][3] += s3 * b.w;
                }
                #pragma unroll
                for (int j = 0; j < 4; j++) {
                    float* p = kv + (4 * ty + j) * CIN + cc * 64 + 4 * tx;
                    float4 old = *reinterpret_cast<float4*>(p);
                    old.x += a2[j][0]; old.y += a2[j][1]; old.z += a2[j][2]; old.w += a2[j][3];
                    *reinterpret_cast<float4*>(p) = old;
                }
            }
        }
        __syncthreads();
    }

    // write deterministic per-block partials
    for (int i = tid; i < DHEAD * CIN; i += 256)
        g_part_kvs[bx][h * DHEAD * CIN + i] = kv[i];
    if (tid < DHEAD) g_part_kss[bx][h * DHEAD + tid] = kss[tid];
    if (h == 0 && tid < CIN) g_part_cs[bx][tid] = cs[tid];
}

// =====================================================================
// Fixed-order reduction of per-block partials
// =====================================================================
__global__ void reduce_kernel()
{
    int i = blockIdx.x * 256 + threadIdx.x;   // 0 .. 65535
    if (i < NHEADS * DHEAD * CIN) {
        float s = 0.f;
        #pragma unroll 1
        for (int b = 0; b < BPH; b++) s += g_part_kvs[b][i];
        g_kvs[i] = s;
    }
    if (i < NHEADS * DHEAD) {
        float s = 0.f;
        for (int b = 0; b < BPH; b++) s += g_part_kss[b][i];
        g_kssum[i] = s;
    }
    if (i < CIN) {
        float s = 0.f;
        for (int b = 0; b < BPH; b++) s += g_part_cs[b][i];
        g_colsum[i] = s;
    }
}

// =====================================================================
// Phase B: q-projection + normalize + output
// =====================================================================
__global__ __launch_bounds__(256, 1)
void phaseB_kernel(const float* __restrict__ x,
                   const float* __restrict__ Wq,
                   const float* __restrict__ bq,
                   float* __restrict__ out)
{
    const int h   = blockIdx.y;
    const int tid = threadIdx.x;
    const int tx  = tid & 15;
    const int ty  = tid >> 4;

    float* xs   = smf;                      // [TILE][XSS]
    float* wt   = xs   + TILE * XSS;        // [CIN][DHEAD] Wq^T chunk
    float* kvs  = wt   + CIN * DHEAD;       // [DHEAD][CIN]
    float* qs   = kvs  + DHEAD * CIN;       // [TILE][KST]
    float* bias = qs   + TILE * KST;        // [DHEAD]
    float* kss  = bias + DHEAD;             // [DHEAD]
    float* cs   = kss  + DHEAD;             // [CIN]
    float* red  = cs   + CIN;               // [256]
    float* red2 = red  + 256;               // [256]
    float* inv  = red2 + 256;               // [TILE]
    float* rno  = inv  + TILE;              // [TILE] reciprocal normalizer

    for (int i = tid; i < DHEAD * CIN; i += 256) {
        int c = i & (CIN - 1);
        int m = i >> 8;
        wt[c * DHEAD + m] = Wq[(h * DHEAD + m) * CIN + c];
    }
    for (int i = tid; i < DHEAD * CIN; i += 256) kvs[i] = g_kvs[h * DHEAD * CIN + i];
    if (tid < DHEAD) { bias[tid] = bq[h * DHEAD + tid]; kss[tid] = g_kssum[h * DHEAD + tid]; }
    if (tid < CIN)   cs[tid] = g_colsum[tid];
    __syncthreads();

    for (int tile = blockIdx.x; tile < NT; tile += BPH) {
        const int base  = tile * TILE;
        int valid = NNODES - base; if (valid > TILE) valid = TILE;

        for (int i = tid; i < TILE * 64; i += 256) {
            int n  = i >> 6;
            int c4 = (i & 63) << 2;
            float4 v = make_float4(0.f, 0.f, 0.f, 0.f);
            if (n < valid)
                v = *reinterpret_cast<const float4*>(x + (size_t)(base + n) * CIN + c4);
            *reinterpret_cast<float4*>(xs + n * XSS + c4) = v;
        }
        __syncthreads();

        // q-projection
        float acc[4][4];
        #pragma unroll
        for (int j = 0; j < 4; j++) { acc[j][0]=0.f; acc[j][1]=0.f; acc[j][2]=0.f; acc[j][3]=0.f; }
        {
            const float* xr0 = xs + (4 * ty + 0) * XSS;
            const float* xr1 = xr0 + XSS;
            const float* xr2 = xr1 + XSS;
            const float* xr3 = xr2 + XSS;
            const float* wp  = wt + 4 * tx;
            #pragma unroll 8
            for (int c = 0; c < CIN; c++) {
                float4 b = *reinterpret_cast<const float4*>(wp + c * DHEAD);
                float a0 = xr0[c], a1 = xr1[c], a2 = xr2[c], a3 = xr3[c];
                acc[0][0] += a0 * b.x; acc[0][1] += a0 * b.y; acc[0][2] += a0 * b.z; acc[0][3] += a0 * b.w;
                acc[1][0] += a1 * b.x; acc[1][1] += a1 * b.y; acc[1][2] += a1 * b.z; acc[1][3] += a1 * b.w;
                acc[2][0] += a2 * b.x; acc[2][1] += a2 * b.y; acc[2][2] += a2 * b.z; acc[2][3] += a2 * b.w;
                acc[3][0] += a3 * b.x; acc[3][1] += a3 * b.y; acc[3][2] += a3 * b.z; acc[3][3] += a3 * b.w;
            }
        }
        {
            float4 bb = *reinterpret_cast<const float4*>(bias + 4 * tx);
            #pragma unroll
            for (int j = 0; j < 4; j++) {
                float4 v;
                v.x = acc[j][0] + bb.x; v.y = acc[j][1] + bb.y;
                v.z = acc[j][2] + bb.z; v.w = acc[j][3] + bb.w;
                *reinterpret_cast<float4*>(qs + (4 * ty + j) * KST + 4 * tx) = v;
            }
        }
        __syncthreads();

        // row norms + dot(P, ks_sum) in one pass
        {
            int n = tid >> 2, q = tid & 3;
            const float* qr = qs + n * KST + q * 16;
            const float* kr = kss + q * 16;
            float s = 0.f, d = 0.f;
            #pragma unroll
            for (int i = 0; i < 16; i++) { float v = qr[i]; s += v * v; d += v * kr[i]; }
            red [n * 4 + q] = s;
            red2[n * 4 + q] = d;
        }
        __syncthreads();
        if (tid < TILE) {
            float s = red [tid*4] + red [tid*4+1] + red [tid*4+2] + red [tid*4+3];
            float d = red2[tid*4] + red2[tid*4+1] + red2[tid*4+2] + red2[tid*4+3];
            float iv = (tid < valid) ? rsqrtf(s) : 0.f;
            inv[tid] = iv;
            rno[tid] = 1.0f / (iv * d + (float)NNODES);
        }
        __syncthreads();
        for (int i = tid; i < TILE * DHEAD; i += 256) {
            int n = i >> 6, m = i & 63;
            qs[n * KST + m] *= inv[n];
        }
        __syncthreads();

        // out[n][c] = (sum_m qs[n][m]*kvs[m][c] + colsum[c]) * rno[n]
        {
            const float* qp = qs + 4 * ty * KST;
            #pragma unroll
            for (int cc = 0; cc < 4; cc++) {
                float a2[4][4];
                #pragma unroll
                for (int j = 0; j < 4; j++) { a2[j][0]=0.f; a2[j][1]=0.f; a2[j][2]=0.f; a2[j][3]=0.f; }
                const float* kp2 = kvs + cc * 64 + 4 * tx;
                #pragma unroll 8
                for (int m = 0; m < DHEAD; m++) {
                    float4 b = *reinterpret_cast<const float4*>(kp2 + m * CIN);
                    float s0 = qp[0*KST+m], s1 = qp[1*KST+m], s2 = qp[2*KST+m], s3 = qp[3*KST+m];
                    a2[0][0] += s0 * b.x; a2[0][1] += s0 * b.y; a2[0][2] += s0 * b.z; a2[0][3] += s0 * b.w;
                    a2[1][0] += s1 * b.x; a2[1][1] += s1 * b.y; a2[1][2] += s1 * b.z; a2[1][3] += s1 * b.w;
                    a2[2][0] += s2 * b.x; a2[2][1] += s2 * b.y; a2[2][2] += s2 * b.z; a2[2][3] += s2 * b.w;
                    a2[3][0] += s3 * b.x; a2[3][1] += s3 * b.y; a2[3][2] += s3 * b.z; a2[3][3] += s3 * b.w;
                }
                float4 cv = *reinterpret_cast<const float4*>(cs + cc * 64 + 4 * tx);
                #pragma unroll
                for (int j = 0; j < 4; j++) {
                    int n = 4 * ty + j;
                    if (n < valid) {
                        float r = rno[n];
                        float4 o;
                        o.x = (a2[j][0] + cv.x) * r;
                        o.y = (a2[j][1] + cv.y) * r;
                        o.z = (a2[j][2] + cv.z) * r;
                        o.w = (a2[j][3] + cv.w) * r;
                        *reinterpret_cast<float4*>(
                            out + (size_t)(base + n) * (NHEADS * CIN) + h * CIN + cc * 64 + 4 * tx) = o;
                    }
                }
            }
        }
        __syncthreads();
    }
}

// =====================================================================
extern "C" void kernel_launch(void* const* d_in, const int* in_sizes, int n_in,
                              void* d_out, int out_size)
{
    const float* x    = (const float*)d_in[0];
    const float* Wq_w = (const float*)d_in[1];
    const float* Wq_b = (const float*)d_in[2];
    const float* Wk_w = (const float*)d_in[3];
    const float* Wk_b = (const float*)d_in[4];
    float* out = (float*)d_out;

    const int smemA = (TILE*XSS + CIN*DHEAD + DHEAD*CIN + TILE*KST
                       + DHEAD + DHEAD + CIN + 256 + TILE) * (int)sizeof(float);
    const int smemB = (TILE*XSS + CIN*DHEAD + DHEAD*CIN + TILE*KST
                       + DHEAD + DHEAD + CIN + 256 + 256 + TILE + TILE) * (int)sizeof(float);

    cudaFuncSetAttribute(phaseA_kernel, cudaFuncAttributeMaxDynamicSharedMemorySize, smemA);
    cudaFuncSetAttribute(phaseB_kernel, cudaFuncAttributeMaxDynamicSharedMemorySize, smemB);

    phaseA_kernel<<<dim3(BPH, NHEADS), 256, smemA>>>(x, Wk_w, Wk_b);
    reduce_kernel<<<256, 256>>>();
    phaseB_kernel<<<dim3(BPH, NHEADS), 256, smemB>>>(x, Wq_w, Wq_b, out);
}